// round 15
// baseline (speedup 1.0000x reference)
#include <cuda_runtime.h>
#include <cuda_bf16.h>
#include <cstdint>
#include <math.h>

// Problem shapes (fixed for this bench)
#define BATCH 2
#define DK 128
#define DV 512
#define NQ 4096         // H*W
#define NM 8192         // T*H*W
#define NTHREADS 256
#define PSCALAR 40.0f
// -ln(1e-12) + 8.0 slack for bf16 screening error (~11 sigma)
#define DELTAS 35.6310211159f
#define DELTAE 27.6310211159f   // exact window for final softmax terms

#define QTILE 128
#define MC 64
#define NSEG 8
#define GRIDX 444
#define CAP 1024
#define FCAND 64

// qk smem layout (bytes): A 128 rows x 256B + 2 B bufs of 64 rows x 256B
#define SMQ_A 512
#define SMQ_B (512 + 32768)
#define SMQ_TOTAL (SMQ_B + 2 * 16384)   // 66048 B -> 3 CTAs/SM

// packtrans role block counts (pack + zero only; transpose fused into qk)
#define PK_BLKS  ((NQ + NM) / 32 * 2 * BATCH)              // 1536
#define ZO_BLKS  ((BATCH * DV * NQ / 4) / NTHREADS)        // 4096

// transpose work items fused into qk kernel
#define TR_ITEMS ((NM / 32) * ((DK + DV) / 32) * BATCH)    // 10240

typedef unsigned long long ull;

// -------- device scratch (static: no allocations allowed) --------
__device__ uint32_t g_qkr[(size_t)BATCH * NQ * 64];   // packed bf16x2 rows [b][q][kp]
__device__ uint32_t g_mkr[(size_t)BATCH * NM * 64];   // packed bf16x2 rows [b][m][kp]
__device__ float    g_mkT[(size_t)BATCH * NM * DK];   // exact mkey rows [b][m][d]
__device__ float    g_mvT[(size_t)BATCH * NM * DV];   // exact mval rows [b][m][v]
__device__ int      g_qlist[BATCH * NQ];
__device__ int      g_mlist[BATCH * NM];
__device__ int      g_nq[BATCH];
__device__ int      g_nm[BATCH];
__device__ int2     g_cand[(size_t)BATCH * NQ * CAP];  // (m_compact, logit bits)
__device__ int      g_ccnt[BATCH * NQ];

__device__ __forceinline__ unsigned fenc(float f) {
    unsigned u = __float_as_uint(f);
    return (u & 0x80000000u) ? ~u : (u | 0x80000000u);
}
__device__ __forceinline__ float fdec(unsigned e) {
    unsigned u = (e & 0x80000000u) ? (e & 0x7FFFFFFFu) : ~e;
    return __uint_as_float(u);
}
__device__ __forceinline__ uint32_t smem_u32(const void* p) {
    uint32_t a;
    asm("{ .reg .u64 t; cvta.to.shared.u64 t, %1; cvt.u32.u64 %0, t; }" : "=r"(a) : "l"(p));
    return a;
}

#define MMA_BF16(c0, c1, c2, c3, a0, a1, a2, a3, b0, b1) \
    asm volatile("mma.sync.aligned.m16n8k16.row.col.f32.bf16.bf16.f32 " \
        "{%0,%1,%2,%3}, {%4,%5,%6,%7}, {%8,%9}, {%0,%1,%2,%3};" \
        : "+f"(c0), "+f"(c1), "+f"(c2), "+f"(c3) \
        : "r"(a0), "r"(a1), "r"(a2), "r"(a3), "r"(b0), "r"(b1))

#define LDSM_X4(r0, r1, r2, r3, addr) \
    asm volatile("ldmatrix.sync.aligned.m8n8.x4.shared.b16 {%0,%1,%2,%3}, [%4];" \
        : "=r"(r0), "=r"(r1), "=r"(r2), "=r"(r3) : "r"(addr))

// -------- kernel 1: deterministic stream compaction + ccnt zero --------
__global__ void compact_kernel(const unsigned int* qmask, const unsigned int* mmask) {
    int b = blockIdx.x;
    int which = blockIdx.y;    // 0 = q, 1 = m
    const unsigned int* mask = which ? (mmask + b * NM) : (qmask + b * NQ);
    int n = which ? NM : NQ;
    int* list = which ? (g_mlist + b * NM) : (g_qlist + b * NQ);

    // zero g_ccnt: 4 blocks cover BATCH*NQ ints
    {
        int blk = b * 2 + which;   // 0..3
        int per = BATCH * NQ / 4;
        for (int i = threadIdx.x; i < per; i += NTHREADS)
            g_ccnt[blk * per + i] = 0;
    }

    __shared__ int wcnt[NTHREADS / 32];
    __shared__ int sbase;
    int tid = threadIdx.x, lane = tid & 31, wid = tid >> 5;
    if (tid == 0) sbase = 0;
    __syncthreads();

    for (int start = 0; start < n; start += NTHREADS) {
        int idx = start + tid;
        int flag = (idx < n) && (mask[idx] != 0u);
        unsigned bal = __ballot_sync(0xFFFFFFFFu, flag);
        int pre = __popc(bal & ((1u << lane) - 1u));
        if (lane == 0) wcnt[wid] = __popc(bal);
        __syncthreads();
        int wbase = 0, tot = 0;
#pragma unroll
        for (int w = 0; w < NTHREADS / 32; w++) {
            if (w < wid) wbase += wcnt[w];
            tot += wcnt[w];
        }
        int base = sbase;
        if (flag) list[base + wbase + pre] = idx;
        __syncthreads();
        if (tid == 0) sbase = base + tot;
        __syncthreads();
    }
    if (tid == 0) {
        if (which) g_nm[b] = sbase; else g_nq[b] = sbase;
    }
}

// -------- kernel 2: fused pack (bf16 rows) + output zero --------
__global__ void packtrans_kernel(const float* __restrict__ qkey, const float* __restrict__ mkey,
                                 float4* __restrict__ out) {
    __shared__ float t[32][66];
    int bx = blockIdx.x;
    int tid = threadIdx.x;
    int tx = tid & 31, ty = tid >> 5;   // 32 x 8

    if (bx < PK_BLKS) {
        // ---- pack role ----
        int rb = bx % ((NQ + NM) / 32);
        int half = (bx / ((NQ + NM) / 32)) & 1;
        int b = bx / ((NQ + NM) / 32 * 2);
        bool isq = rb < (NQ / 32);
        int base = isq ? rb * 32 : (rb - NQ / 32) * 32;
        int n = isq ? g_nq[b] : g_nm[b];
        int N = isq ? NQ : NM;
        const int* list = (isq ? g_qlist : g_mlist) + b * N;
        const float* src = (isq ? qkey : mkey) + (size_t)(b * DK + half * 64) * N;
        uint32_t* dst = (isq ? g_qkr : g_mkr) + ((size_t)b * N + base) * 64 + half * 32;

        int i = base + tx;
        int g = (i < n) ? list[i] : -1;
#pragma unroll
        for (int dd = ty; dd < 64; dd += 8)
            t[tx][dd] = (g >= 0) ? src[(size_t)dd * N + g] : 0.f;
        __syncthreads();
#pragma unroll
        for (int mi = ty; mi < 32; mi += 8) {
            float2 v = *(float2*)&t[mi][2 * tx];
            __nv_bfloat162 w = __floats2bfloat162_rn(v.x, v.y);
            dst[(size_t)mi * 64 + tx] = *(uint32_t*)&w;
        }
    } else {
        // ---- zero-output role ----
        int idx = (bx - PK_BLKS) * NTHREADS + tid;
        out[idx] = make_float4(0.f, 0.f, 0.f, 0.f);
    }
}

// -------- kernel 3: bf16 mma.sync screening GEMM + fused exact transpose items --------
__global__ __launch_bounds__(NTHREADS, 3)
void qk_mma_kernel(const float* __restrict__ mkey, const float* __restrict__ mval) {
    extern __shared__ char smem[];
    uint32_t sbase = smem_u32(smem);
    unsigned* sGMax = (unsigned*)smem;
    uint32_t sAu = sbase + SMQ_A, sBu = sbase + SMQ_B;
    float (*tt)[33] = (float (*)[33])(smem + SMQ_A);   // transpose overlay (4224 B)

    int tid = threadIdx.x, lane = tid & 31, wid = tid >> 5;
    int gr = lane >> 2, tig = lane & 3;
    int warp_q0 = (wid >> 2) * 64;
    int warp_m0 = (wid & 3) * 16;

    int nt0 = (g_nm[0] > 0) ? ((g_nq[0] + 127) >> 7) : 0;
    int nt1 = (g_nm[1] > 0) ? ((g_nq[1] + 127) >> 7) : 0;
    int totalG = (nt0 + nt1) * NSEG;
    int total = totalG + TR_ITEMS;

    int a_row_off = (lane & 15);
    int a_k16 = (lane >> 4) << 4;
    int b_row_off = (lane & 7) + ((lane & 16) >> 1);
    int b_k16 = (lane & 8) << 1;

    int tx = tid & 31, ty = tid >> 5;   // for transpose role

    for (int item = blockIdx.x; item < total; item += gridDim.x) {
        if (item >= totalG) {
            // ---- transpose work item: one 32x32 tile of mkey/mval gather-transpose ----
            __syncthreads();   // protect smem overlay from prior item's readers
            int idx = item - totalG;
            int m0 = (idx % (NM / 32)) * 32;
            int d0 = ((idx / (NM / 32)) % ((DK + DV) / 32)) * 32;
            int b = idx / ((NM / 32) * ((DK + DV) / 32));
            int nm = g_nm[b];
            if (m0 >= nm) continue;
            bool ismk = d0 < DK;
            const float* src = ismk ? (mkey + (size_t)(b * DK + d0) * NM)
                                    : (mval + (size_t)b * DV * NM + (size_t)(d0 - DK) * NM);
            int mg = (m0 + tx < nm) ? g_mlist[b * NM + m0 + tx] : 0;
#pragma unroll
            for (int i = ty; i < 32; i += 8)
                tt[tx][i] = src[(size_t)i * NM + mg];
            __syncthreads();
#pragma unroll
            for (int i = ty; i < 32; i += 8) {
                int m = m0 + i;
                if (m < nm) {
                    if (ismk) g_mkT[((size_t)b * NM + m) * DK + d0 + tx] = tt[i][tx];
                    else      g_mvT[((size_t)b * NM + m) * DV + (d0 - DK) + tx] = tt[i][tx];
                }
            }
            continue;
        }

        // ---- GEMM work item ----
        int tq = item / NSEG, seg = item - tq * NSEG;
        int b = (tq < nt0) ? 0 : 1;
        int qt = (tq < nt0) ? tq : tq - nt0;
        int nq = g_nq[b], nm = g_nm[b];
        int qi0 = qt * QTILE;
        int segsz = ((((nm + NSEG - 1) / NSEG) + MC - 1) / MC) * MC;
        int ms = seg * segsz;
        if (ms >= nm) continue;
        int me = min(ms + segsz, nm);
        int nch = (me - ms + MC - 1) / MC;

        __syncthreads();
        if (tid < QTILE) sGMax[tid] = fenc(-3.0e38f);

        // stage A tile: 128 rows x 256B = 2048 16B chunks, swizzled
        {
            const uint32_t* arows = g_qkr + ((size_t)b * NQ + qi0) * 64;
#pragma unroll
            for (int k2 = 0; k2 < 8; k2++) {
                int idx = tid + k2 * NTHREADS;
                int row = idx >> 4, ch = idx & 15;
                uint32_t doff = (uint32_t)((row << 8) + (ch << 4));
                doff ^= (uint32_t)((row & 7) << 4);
                const uint32_t* src = arows + row * 64 + ch * 4;
                asm volatile("cp.async.cg.shared.global [%0], [%1], 16;"
                             :: "r"(sAu + doff), "l"(src));
            }
            asm volatile("cp.async.commit_group;");
        }

        auto issueB = [&](int m0, int buf) {
            const uint32_t* brows = g_mkr + ((size_t)b * NM + m0) * 64;
            uint32_t bb = sBu + buf * 16384;
#pragma unroll
            for (int k2 = 0; k2 < 4; k2++) {
                int idx = tid + k2 * NTHREADS;
                int row = idx >> 4, ch = idx & 15;
                uint32_t doff = (uint32_t)((row << 8) + (ch << 4));
                doff ^= (uint32_t)((row & 7) << 4);
                const uint32_t* src = brows + row * 64 + ch * 4;
                asm volatile("cp.async.cg.shared.global [%0], [%1], 16;"
                             :: "r"(bb + doff), "l"(src));
            }
            asm volatile("cp.async.commit_group;");
        };

        issueB(ms, 0);

        for (int c = 0; c < nch; c++) {
            int mt0 = ms + c * MC;
            asm volatile("cp.async.wait_group 0;");
            __syncthreads();
            if (c + 1 < nch) issueB(ms + (c + 1) * MC, (c + 1) & 1);

            uint32_t sBc = sBu + (c & 1) * 16384;

            float acc[4][2][4];
#pragma unroll
            for (int qf = 0; qf < 4; qf++)
#pragma unroll
                for (int nf = 0; nf < 2; nf++)
#pragma unroll
                    for (int r = 0; r < 4; r++) acc[qf][nf][r] = 0.f;

#pragma unroll
            for (int s = 0; s < 8; s++) {
                uint32_t a[4][4], bf[4];
#pragma unroll
                for (int qf = 0; qf < 4; qf++) {
                    int row = warp_q0 + qf * 16 + a_row_off;
                    uint32_t off = (uint32_t)((row << 8) + (s << 5) + a_k16)
                                 ^ (uint32_t)((row & 7) << 4);
                    LDSM_X4(a[qf][0], a[qf][1], a[qf][2], a[qf][3], sAu + off);
                }
                {
                    int row = warp_m0 + b_row_off;
                    uint32_t off = (uint32_t)((row << 8) + (s << 5) + b_k16)
                                 ^ (uint32_t)((row & 7) << 4);
                    LDSM_X4(bf[0], bf[1], bf[2], bf[3], sBc + off);
                }
#pragma unroll
                for (int qf = 0; qf < 4; qf++)
#pragma unroll
                    for (int nf = 0; nf < 2; nf++)
                        MMA_BF16(acc[qf][nf][0], acc[qf][nf][1], acc[qf][nf][2], acc[qf][nf][3],
                                 a[qf][0], a[qf][1], a[qf][2], a[qf][3],
                                 bf[nf * 2], bf[nf * 2 + 1]);
            }

            // epilogue: per q-row block max + rare candidate emission
            int mbw = mt0 + warp_m0;
#pragma unroll
            for (int qf = 0; qf < 4; qf++) {
#pragma unroll
                for (int h = 0; h < 2; h++) {
                    int qrow = warp_q0 + qf * 16 + gr + h * 8;
                    int q = qi0 + qrow;
                    float sv[4];
                    float bm = -3.0e38f;
#pragma unroll
                    for (int nf = 0; nf < 2; nf++)
#pragma unroll
                        for (int col = 0; col < 2; col++) {
                            int ii = nf * 2 + col;
                            sv[ii] = acc[qf][nf][h * 2 + col] * PSCALAR;
                            int mg = mbw + nf * 8 + 2 * tig + col;
                            if (mg < me) bm = fmaxf(bm, sv[ii]);
                        }
                    if (q < nq && bm > fdec(sGMax[qrow]) - DELTAS) {
                        unsigned olde = atomicMax(&sGMax[qrow], fenc(bm));
                        float th = fmaxf(fdec(olde), bm);
#pragma unroll
                        for (int nf = 0; nf < 2; nf++)
#pragma unroll
                            for (int col = 0; col < 2; col++) {
                                int ii = nf * 2 + col;
                                int mg = mbw + nf * 8 + 2 * tig + col;
                                if (mg < me && sv[ii] > th - DELTAS) {
                                    int pos = atomicAdd(&g_ccnt[b * NQ + q], 1);
                                    if (pos < CAP)
                                        g_cand[((size_t)b * NQ + q) * CAP + pos] =
                                            make_int2(mg, __float_as_int(sv[ii]));
                                }
                            }
                    }
                }
            }
        }
    }
}

// -------- kernel 4: finalize — lane-parallel exact logits + 2-phase pass C --------
__global__ __launch_bounds__(NTHREADS)
void finalize_kernel(const float* __restrict__ qkey, float* __restrict__ out) {
    __shared__ __align__(16) float sQc[8 * DK];   // 4 KB
    __shared__ int2  sCand[8][FCAND];             // 4 KB
    __shared__ float sO[8][DV + 4];               // 16.1 KB
    __shared__ int   sQg[8];
    int b = blockIdx.y;
    int nq = g_nq[b], nm = g_nm[b];
    if (nm == 0) return;
    int tid = threadIdx.x, wid = tid >> 5, lane = tid & 31;
    int q = blockIdx.x * 8 + wid;
    bool valid = (q < nq);

    int qg = 0, c = 0;
    size_t cbase = 0;
    if (valid) {
        qg = g_qlist[b * NQ + q];
        cbase = ((size_t)b * NQ + q) * CAP;
        c = min(g_ccnt[b * NQ + q], CAP);
    }
    if (lane == 0) sQg[wid] = valid ? qg : -1;

    if (valid) {
        for (int d = lane; d < DK; d += 32)
            sQc[wid * DK + d] = qkey[(size_t)(b * DK + d) * NQ + qg];
        for (int i = lane; i < c && i < FCAND; i += 32)
            sCand[wid][i] = g_cand[cbase + i];
    }
    __syncwarp();

    float inv = 0.f, mx = -3.0e38f;
    if (valid) {
        float mxs = -3.0e38f;
        for (int i = lane; i < c; i += 32) {
            int2 e = (i < FCAND) ? sCand[wid][i] : g_cand[cbase + i];
            mxs = fmaxf(mxs, __int_as_float(e.y));
        }
#pragma unroll
        for (int off = 16; off; off >>= 1)
            mxs = fmaxf(mxs, __shfl_xor_sync(0xFFFFFFFFu, mxs, off));

        // pass A: lane-parallel exact fp32 logits
        const float* mkT = g_mkT + (size_t)b * NM * DK;
        const float4* q4 = (const float4*)&sQc[wid * DK];
        for (int i = lane; i < c; i += 32) {
            int2 e = (i < FCAND) ? sCand[wid][i] : g_cand[cbase + i];
            float snew = -3.0e38f;
            if (__int_as_float(e.y) > mxs - DELTAS) {
                const float4* r4 = (const float4*)(mkT + (size_t)e.x * DK);
                float a0 = 0.f, a1 = 0.f, a2 = 0.f, a3 = 0.f;
#pragma unroll 8
                for (int j = 0; j < DK / 4; j++) {
                    float4 mv = r4[j];
                    float4 qv = q4[j];
                    a0 = fmaf(qv.x, mv.x, a0);
                    a1 = fmaf(qv.y, mv.y, a1);
                    a2 = fmaf(qv.z, mv.z, a2);
                    a3 = fmaf(qv.w, mv.w, a3);
                }
                snew = ((a0 + a1) + (a2 + a3)) * PSCALAR;
                mx = fmaxf(mx, snew);
            }
            if (i < FCAND) sCand[wid][i].y = __float_as_int(snew);
            else g_cand[cbase + i].y = __float_as_int(snew);
        }
        __syncwarp();
#pragma unroll
        for (int off = 16; off; off >>= 1)
            mx = fmaxf(mx, __shfl_xor_sync(0xFFFFFFFFu, mx, off));

        // pass B: deterministic fixed-point exp sum over exact-window terms
        float thE = mx - DELTAE;
        unsigned long long iacc = 0;
        for (int i = lane; i < c; i += 32) {
            float s = __int_as_float((i < FCAND) ? sCand[wid][i].y : g_cand[cbase + i].y);
            if (s > thE) {
                float w = expf(s - mx);
                iacc += (unsigned long long)((double)w * 4503599627370496.0);  // 2^52
            }
        }
#pragma unroll
        for (int off = 16; off; off >>= 1)
            iacc += __shfl_xor_sync(0xFFFFFFFFu, iacc, off);
        double dsum = (double)iacc * (1.0 / 4503599627370496.0);
        inv = (float)(1.0 / dsum);

        // pass C, phase 1: extract kept events (ascending m) into distributed registers
        float ov[16];
#pragma unroll
        for (int j = 0; j < 16; j++) ov[j] = 0.f;

        const float* mvT = g_mvT + (size_t)b * NM * DV;
        int last = -1;
        while (true) {
            int evm_r = 0; float evw_r = 0.f;
            int cnt = 0;
            while (cnt < 32) {
                int mym = 0x7FFFFFFF; float myw = 0.f;
                for (int i = lane; i < c; i += 32) {
                    int2 e = (i < FCAND) ? sCand[wid][i] : g_cand[cbase + i];
                    float s = __int_as_float(e.y);
                    if (s > thE && e.x > last && e.x < mym) {
                        mym = e.x;
                        myw = expf(s - mx);
                    }
                }
#pragma unroll
                for (int off = 16; off; off >>= 1) {
                    int om = __shfl_xor_sync(0xFFFFFFFFu, mym, off);
                    float ow = __shfl_xor_sync(0xFFFFFFFFu, myw, off);
                    if (om < mym) { mym = om; myw = ow; }
                }
                if (mym == 0x7FFFFFFF) break;
                if (lane == cnt) { evm_r = mym; evw_r = myw; }
                last = mym;
                cnt++;
            }
            if (cnt == 0) break;

            // pass C, phase 2: gather rows, 2 events in flight (deterministic order)
            int e = 0;
            for (; e + 1 < cnt; e += 2) {
                int m0 = __shfl_sync(0xFFFFFFFFu, evm_r, e);
                float w0 = __shfl_sync(0xFFFFFFFFu, evw_r, e);
                int m1 = __shfl_sync(0xFFFFFFFFu, evm_r, e + 1);
                float w1 = __shfl_sync(0xFFFFFFFFu, evw_r, e + 1);
                const float* r0 = mvT + (size_t)m0 * DV;
                const float* r1 = mvT + (size_t)m1 * DV;
#pragma unroll
                for (int j = 0; j < 16; j++) {
                    float v0 = r0[lane + 32 * j];
                    float v1 = r1[lane + 32 * j];
                    ov[j] += w0 * v0;
                    ov[j] += w1 * v1;
                }
            }
            if (e < cnt) {
                int m0 = __shfl_sync(0xFFFFFFFFu, evm_r, e);
                float w0 = __shfl_sync(0xFFFFFFFFu, evw_r, e);
                const float* r0 = mvT + (size_t)m0 * DV;
#pragma unroll
                for (int j = 0; j < 16; j++)
                    ov[j] += w0 * r0[lane + 32 * j];
            }
            if (cnt < 32) break;   // fewer than a full batch -> no more events
        }

#pragma unroll
        for (int j = 0; j < 16; j++)
            sO[wid][lane + 32 * j] = ov[j] * inv;
    }
    __syncthreads();

    float* ob = out + (size_t)b * DV * NQ;
    for (int idx = tid; idx < 8 * DV; idx += NTHREADS) {
        int v = idx >> 3, k = idx & 7;
        int qgk = sQg[k];
        if (qgk >= 0) ob[(size_t)v * NQ + qgk] = sO[k][v];
    }
}

// -------- launch --------
extern "C" void kernel_launch(void* const* d_in, const int* in_sizes, int n_in,
                              void* d_out, int out_size) {
    const float*        qkey  = (const float*)d_in[0];
    // d_in[1] = qval (unused by the reference math)
    const unsigned int* qmask = (const unsigned int*)d_in[2];
    const float*        mkey  = (const float*)d_in[3];
    const float*        mval  = (const float*)d_in[4];
    const unsigned int* mmask = (const unsigned int*)d_in[5];
    float* out = (float*)d_out;

    compact_kernel<<<dim3(BATCH, 2), NTHREADS>>>(qmask, mmask);

    packtrans_kernel<<<PK_BLKS + ZO_BLKS, NTHREADS>>>(qkey, mkey, (float4*)out);

    cudaFuncSetAttribute(qk_mma_kernel, cudaFuncAttributeMaxDynamicSharedMemorySize, SMQ_TOTAL);
    qk_mma_kernel<<<GRIDX, NTHREADS, SMQ_TOTAL>>>(mkey, mval);

    // launch #4 — ncu capture slot: finalize
    finalize_kernel<<<dim3(NQ / 8, BATCH), NTHREADS>>>(qkey, out);
}

// round 16
// speedup vs baseline: 1.2063x; 1.2063x over previous
#include <cuda_runtime.h>
#include <cuda_bf16.h>
#include <cstdint>
#include <math.h>

// Problem shapes (fixed for this bench)
#define BATCH 2
#define DK 128
#define DV 512
#define NQ 4096         // H*W
#define NM 8192         // T*H*W
#define NTHREADS 256
#define PSCALAR 40.0f
// -ln(1e-12) + 8.0 slack for bf16 screening error (~11 sigma)
#define DELTAS 35.6310211159f
#define DELTAE 27.6310211159f   // exact window for final softmax terms

#define QTILE 128
#define MC 64
#define NSEG 8
#define GRIDX 444
#define CAP 1024
#define FCAND 64

// qk smem layout (bytes): A 128 rows x 256B + 2 B bufs of 64 rows x 256B
#define SMQ_A 512
#define SMQ_B (512 + 32768)
#define SMQ_TOTAL (SMQ_B + 2 * 16384)   // 66048 B -> 3 CTAs/SM

// packtrans role block counts
#define PK_BLKS  ((NQ + NM) / 32 * 2 * BATCH)              // 1536
#define TR_BLKS  ((NM / 32) * ((DK + DV) / 32) * BATCH)    // 10240
#define ZO_BLKS  ((BATCH * DV * NQ / 4) / NTHREADS)        // 4096

typedef unsigned long long ull;

// -------- device scratch (static: no allocations allowed) --------
__device__ uint32_t g_qkr[(size_t)BATCH * NQ * 64];   // packed bf16x2 rows [b][q][kp]
__device__ uint32_t g_mkr[(size_t)BATCH * NM * 64];   // packed bf16x2 rows [b][m][kp]
__device__ float    g_mkT[(size_t)BATCH * NM * DK];   // exact mkey rows [b][m][d]
__device__ float    g_mvT[(size_t)BATCH * NM * DV];   // exact mval rows [b][m][v]
__device__ int      g_qlist[BATCH * NQ];
__device__ int      g_mlist[BATCH * NM];
__device__ int      g_nq[BATCH];
__device__ int      g_nm[BATCH];
__device__ int2     g_cand[(size_t)BATCH * NQ * CAP];  // (m_compact, logit bits)
__device__ int      g_ccnt[BATCH * NQ];
__device__ unsigned g_qmax[BATCH * NQ];                // cross-segment running screened max

__device__ __forceinline__ unsigned fenc(float f) {
    unsigned u = __float_as_uint(f);
    return (u & 0x80000000u) ? ~u : (u | 0x80000000u);
}
__device__ __forceinline__ float fdec(unsigned e) {
    unsigned u = (e & 0x80000000u) ? (e & 0x7FFFFFFFu) : ~e;
    return __uint_as_float(u);
}
__device__ __forceinline__ uint32_t smem_u32(const void* p) {
    uint32_t a;
    asm("{ .reg .u64 t; cvta.to.shared.u64 t, %1; cvt.u32.u64 %0, t; }" : "=r"(a) : "l"(p));
    return a;
}

#define MMA_BF16(c0, c1, c2, c3, a0, a1, a2, a3, b0, b1) \
    asm volatile("mma.sync.aligned.m16n8k16.row.col.f32.bf16.bf16.f32 " \
        "{%0,%1,%2,%3}, {%4,%5,%6,%7}, {%8,%9}, {%0,%1,%2,%3};" \
        : "+f"(c0), "+f"(c1), "+f"(c2), "+f"(c3) \
        : "r"(a0), "r"(a1), "r"(a2), "r"(a3), "r"(b0), "r"(b1))

#define LDSM_X4(r0, r1, r2, r3, addr) \
    asm volatile("ldmatrix.sync.aligned.m8n8.x4.shared.b16 {%0,%1,%2,%3}, [%4];" \
        : "=r"(r0), "=r"(r1), "=r"(r2), "=r"(r3) : "r"(addr))

// -------- kernel 1: deterministic stream compaction + ccnt/qmax init --------
__global__ void compact_kernel(const unsigned int* qmask, const unsigned int* mmask) {
    int b = blockIdx.x;
    int which = blockIdx.y;    // 0 = q, 1 = m
    const unsigned int* mask = which ? (mmask + b * NM) : (qmask + b * NQ);
    int n = which ? NM : NQ;
    int* list = which ? (g_mlist + b * NM) : (g_qlist + b * NQ);

    // init g_ccnt and g_qmax: 4 blocks cover BATCH*NQ entries each
    {
        int blk = b * 2 + which;   // 0..3
        int per = BATCH * NQ / 4;
        unsigned neg = fenc(-3.0e38f);
        for (int i = threadIdx.x; i < per; i += NTHREADS) {
            g_ccnt[blk * per + i] = 0;
            g_qmax[blk * per + i] = neg;
        }
    }

    __shared__ int wcnt[NTHREADS / 32];
    __shared__ int sbase;
    int tid = threadIdx.x, lane = tid & 31, wid = tid >> 5;
    if (tid == 0) sbase = 0;
    __syncthreads();

    for (int start = 0; start < n; start += NTHREADS) {
        int idx = start + tid;
        int flag = (idx < n) && (mask[idx] != 0u);
        unsigned bal = __ballot_sync(0xFFFFFFFFu, flag);
        int pre = __popc(bal & ((1u << lane) - 1u));
        if (lane == 0) wcnt[wid] = __popc(bal);
        __syncthreads();
        int wbase = 0, tot = 0;
#pragma unroll
        for (int w = 0; w < NTHREADS / 32; w++) {
            if (w < wid) wbase += wcnt[w];
            tot += wcnt[w];
        }
        int base = sbase;
        if (flag) list[base + wbase + pre] = idx;
        __syncthreads();
        if (tid == 0) sbase = base + tot;
        __syncthreads();
    }
    if (tid == 0) {
        if (which) g_nm[b] = sbase; else g_nq[b] = sbase;
    }
}

// -------- kernel 2: fused pack (bf16 rows) + transpose (exact rows) + output zero --------
__global__ void packtrans_kernel(const float* __restrict__ qkey, const float* __restrict__ mkey,
                                 const float* __restrict__ mval, float4* __restrict__ out) {
    __shared__ float t[32][66];
    int bx = blockIdx.x;
    int tid = threadIdx.x;
    int tx = tid & 31, ty = tid >> 5;   // 32 x 8

    if (bx < PK_BLKS) {
        // ---- pack role ----
        int rb = bx % ((NQ + NM) / 32);
        int half = (bx / ((NQ + NM) / 32)) & 1;
        int b = bx / ((NQ + NM) / 32 * 2);
        bool isq = rb < (NQ / 32);
        int base = isq ? rb * 32 : (rb - NQ / 32) * 32;
        int n = isq ? g_nq[b] : g_nm[b];
        int N = isq ? NQ : NM;
        const int* list = (isq ? g_qlist : g_mlist) + b * N;
        const float* src = (isq ? qkey : mkey) + (size_t)(b * DK + half * 64) * N;
        uint32_t* dst = (isq ? g_qkr : g_mkr) + ((size_t)b * N + base) * 64 + half * 32;

        int i = base + tx;
        int g = (i < n) ? list[i] : -1;
#pragma unroll
        for (int dd = ty; dd < 64; dd += 8)
            t[tx][dd] = (g >= 0) ? src[(size_t)dd * N + g] : 0.f;
        __syncthreads();
#pragma unroll
        for (int mi = ty; mi < 32; mi += 8) {
            float2 v = *(float2*)&t[mi][2 * tx];
            __nv_bfloat162 w = __floats2bfloat162_rn(v.x, v.y);
            dst[(size_t)mi * 64 + tx] = *(uint32_t*)&w;
        }
    } else if (bx < PK_BLKS + TR_BLKS) {
        // ---- transpose role ----
        int idx = bx - PK_BLKS;
        int m0 = (idx % (NM / 32)) * 32;
        int d0 = ((idx / (NM / 32)) % ((DK + DV) / 32)) * 32;
        int b = idx / ((NM / 32) * ((DK + DV) / 32));
        int nm = g_nm[b];
        if (m0 >= nm) return;
        bool ismk = d0 < DK;
        const float* src = ismk ? (mkey + (size_t)(b * DK + d0) * NM)
                                : (mval + (size_t)b * DV * NM + (size_t)(d0 - DK) * NM);
        int mg = (m0 + tx < nm) ? g_mlist[b * NM + m0 + tx] : 0;
#pragma unroll
        for (int i = ty; i < 32; i += 8)
            t[tx][i] = src[(size_t)i * NM + mg];
        __syncthreads();
#pragma unroll
        for (int i = ty; i < 32; i += 8) {
            int m = m0 + i;
            if (m < nm) {
                if (ismk) g_mkT[((size_t)b * NM + m) * DK + d0 + tx] = t[i][tx];
                else      g_mvT[((size_t)b * NM + m) * DV + (d0 - DK) + tx] = t[i][tx];
            }
        }
    } else {
        // ---- zero-output role ----
        int idx = (bx - PK_BLKS - TR_BLKS) * NTHREADS + tid;
        out[idx] = make_float4(0.f, 0.f, 0.f, 0.f);
    }
}

// -------- kernel 3: bf16 mma.sync screening GEMM + cross-segment global suppression --------
__global__ __launch_bounds__(NTHREADS, 3)
void qk_mma_kernel() {
    extern __shared__ char smem[];
    uint32_t sbase = smem_u32(smem);
    unsigned* sGMax = (unsigned*)smem;
    uint32_t sAu = sbase + SMQ_A, sBu = sbase + SMQ_B;

    int tid = threadIdx.x, lane = tid & 31, wid = tid >> 5;
    int gr = lane >> 2, tig = lane & 3;
    int warp_q0 = (wid >> 2) * 64;
    int warp_m0 = (wid & 3) * 16;

    int nt0 = (g_nm[0] > 0) ? ((g_nq[0] + 127) >> 7) : 0;
    int nt1 = (g_nm[1] > 0) ? ((g_nq[1] + 127) >> 7) : 0;
    int total = (nt0 + nt1) * NSEG;

    int a_row_off = (lane & 15);
    int a_k16 = (lane >> 4) << 4;
    int b_row_off = (lane & 7) + ((lane & 16) >> 1);
    int b_k16 = (lane & 8) << 1;

    for (int item = blockIdx.x; item < total; item += gridDim.x) {
        int tq = item / NSEG, seg = item - tq * NSEG;
        int b = (tq < nt0) ? 0 : 1;
        int qt = (tq < nt0) ? tq : tq - nt0;
        int nq = g_nq[b], nm = g_nm[b];
        int qi0 = qt * QTILE;
        int segsz = ((((nm + NSEG - 1) / NSEG) + MC - 1) / MC) * MC;
        int ms = seg * segsz;
        if (ms >= nm) continue;
        int me = min(ms + segsz, nm);
        int nch = (me - ms + MC - 1) / MC;

        __syncthreads();
        // seed from global cross-segment max (stale-read safe: monotone, smaller = permissive)
        if (tid < QTILE) {
            int q = qi0 + tid;
            sGMax[tid] = (q < nq) ? g_qmax[b * NQ + q] : fenc(-3.0e38f);
        }

        // stage A tile: 128 rows x 256B = 2048 16B chunks, swizzled
        {
            const uint32_t* arows = g_qkr + ((size_t)b * NQ + qi0) * 64;
#pragma unroll
            for (int k2 = 0; k2 < 8; k2++) {
                int idx = tid + k2 * NTHREADS;
                int row = idx >> 4, ch = idx & 15;
                uint32_t doff = (uint32_t)((row << 8) + (ch << 4));
                doff ^= (uint32_t)((row & 7) << 4);
                const uint32_t* src = arows + row * 64 + ch * 4;
                asm volatile("cp.async.cg.shared.global [%0], [%1], 16;"
                             :: "r"(sAu + doff), "l"(src));
            }
            asm volatile("cp.async.commit_group;");
        }

        // B chunk: 64 rows x 256B = 1024 16B chunks
        auto issueB = [&](int m0, int buf) {
            const uint32_t* brows = g_mkr + ((size_t)b * NM + m0) * 64;
            uint32_t bb = sBu + buf * 16384;
#pragma unroll
            for (int k2 = 0; k2 < 4; k2++) {
                int idx = tid + k2 * NTHREADS;
                int row = idx >> 4, ch = idx & 15;
                uint32_t doff = (uint32_t)((row << 8) + (ch << 4));
                doff ^= (uint32_t)((row & 7) << 4);
                const uint32_t* src = brows + row * 64 + ch * 4;
                asm volatile("cp.async.cg.shared.global [%0], [%1], 16;"
                             :: "r"(bb + doff), "l"(src));
            }
            asm volatile("cp.async.commit_group;");
        };

        issueB(ms, 0);

        for (int c = 0; c < nch; c++) {
            int mt0 = ms + c * MC;
            asm volatile("cp.async.wait_group 0;");
            __syncthreads();
            if (c + 1 < nch) issueB(ms + (c + 1) * MC, (c + 1) & 1);

            uint32_t sBc = sBu + (c & 1) * 16384;

            float acc[4][2][4];
#pragma unroll
            for (int qf = 0; qf < 4; qf++)
#pragma unroll
                for (int nf = 0; nf < 2; nf++)
#pragma unroll
                    for (int r = 0; r < 4; r++) acc[qf][nf][r] = 0.f;

#pragma unroll
            for (int s = 0; s < 8; s++) {
                uint32_t a[4][4], bf[4];
#pragma unroll
                for (int qf = 0; qf < 4; qf++) {
                    int row = warp_q0 + qf * 16 + a_row_off;
                    uint32_t off = (uint32_t)((row << 8) + (s << 5) + a_k16)
                                 ^ (uint32_t)((row & 7) << 4);
                    LDSM_X4(a[qf][0], a[qf][1], a[qf][2], a[qf][3], sAu + off);
                }
                {
                    int row = warp_m0 + b_row_off;
                    uint32_t off = (uint32_t)((row << 8) + (s << 5) + b_k16)
                                 ^ (uint32_t)((row & 7) << 4);
                    LDSM_X4(bf[0], bf[1], bf[2], bf[3], sBc + off);
                }
#pragma unroll
                for (int qf = 0; qf < 4; qf++)
#pragma unroll
                    for (int nf = 0; nf < 2; nf++)
                        MMA_BF16(acc[qf][nf][0], acc[qf][nf][1], acc[qf][nf][2], acc[qf][nf][3],
                                 a[qf][0], a[qf][1], a[qf][2], a[qf][3],
                                 bf[nf * 2], bf[nf * 2 + 1]);
            }

            // epilogue: per q-row block max + globally-suppressed candidate emission
            int mbw = mt0 + warp_m0;
#pragma unroll
            for (int qf = 0; qf < 4; qf++) {
#pragma unroll
                for (int h = 0; h < 2; h++) {
                    int qrow = warp_q0 + qf * 16 + gr + h * 8;
                    int q = qi0 + qrow;
                    float sv[4];
                    float bm = -3.0e38f;
#pragma unroll
                    for (int nf = 0; nf < 2; nf++)
#pragma unroll
                        for (int col = 0; col < 2; col++) {
                            int ii = nf * 2 + col;
                            sv[ii] = acc[qf][nf][h * 2 + col] * PSCALAR;
                            int mg = mbw + nf * 8 + 2 * tig + col;
                            if (mg < me) bm = fmaxf(bm, sv[ii]);
                        }
                    if (q < nq && bm > fdec(sGMax[qrow]) - DELTAS) {
                        unsigned eb = fenc(bm);
                        unsigned olde = atomicMax(&sGMax[qrow], eb);
                        unsigned oldg = atomicMax(&g_qmax[b * NQ + q], eb);
                        float th = fmaxf(fmaxf(fdec(olde), fdec(oldg)), bm);
#pragma unroll
                        for (int nf = 0; nf < 2; nf++)
#pragma unroll
                            for (int col = 0; col < 2; col++) {
                                int ii = nf * 2 + col;
                                int mg = mbw + nf * 8 + 2 * tig + col;
                                if (mg < me && sv[ii] > th - DELTAS) {
                                    int pos = atomicAdd(&g_ccnt[b * NQ + q], 1);
                                    if (pos < CAP)
                                        g_cand[((size_t)b * NQ + q) * CAP + pos] =
                                            make_int2(mg, __float_as_int(sv[ii]));
                                }
                            }
                    }
                }
            }
        }
    }
}

// -------- kernel 4: finalize — lane-parallel exact logits + softmax + gather --------
__global__ __launch_bounds__(NTHREADS)
void finalize_kernel(const float* __restrict__ qkey, float* __restrict__ out) {
    __shared__ __align__(16) float sQc[8 * DK];   // 4 KB
    __shared__ int2  sCand[8][FCAND];             // 4 KB
    __shared__ float sO[8][DV + 4];               // 16.1 KB
    __shared__ int   sQg[8];
    int b = blockIdx.y;
    int nq = g_nq[b], nm = g_nm[b];
    if (nm == 0) return;
    int tid = threadIdx.x, wid = tid >> 5, lane = tid & 31;
    int q = blockIdx.x * 8 + wid;
    bool valid = (q < nq);

    int qg = 0, c = 0;
    size_t cbase = 0;
    if (valid) {
        qg = g_qlist[b * NQ + q];
        cbase = ((size_t)b * NQ + q) * CAP;
        c = min(g_ccnt[b * NQ + q], CAP);
    }
    if (lane == 0) sQg[wid] = valid ? qg : -1;

    if (valid) {
        for (int d = lane; d < DK; d += 32)
            sQc[wid * DK + d] = qkey[(size_t)(b * DK + d) * NQ + qg];
        for (int i = lane; i < c && i < FCAND; i += 32)
            sCand[wid][i] = g_cand[cbase + i];
    }
    __syncwarp();

    float inv = 0.f, mx = -3.0e38f;
    if (valid) {
        float mxs = -3.0e38f;
        for (int i = lane; i < c; i += 32) {
            int2 e = (i < FCAND) ? sCand[wid][i] : g_cand[cbase + i];
            mxs = fmaxf(mxs, __int_as_float(e.y));
        }
#pragma unroll
        for (int off = 16; off; off >>= 1)
            mxs = fmaxf(mxs, __shfl_xor_sync(0xFFFFFFFFu, mxs, off));

        // pass A: lane-parallel exact fp32 logits
        const float* mkT = g_mkT + (size_t)b * NM * DK;
        const float4* q4 = (const float4*)&sQc[wid * DK];
        for (int i = lane; i < c; i += 32) {
            int2 e = (i < FCAND) ? sCand[wid][i] : g_cand[cbase + i];
            float snew = -3.0e38f;
            if (__int_as_float(e.y) > mxs - DELTAS) {
                const float4* r4 = (const float4*)(mkT + (size_t)e.x * DK);
                float a0 = 0.f, a1 = 0.f, a2 = 0.f, a3 = 0.f;
#pragma unroll 8
                for (int j = 0; j < DK / 4; j++) {
                    float4 mv = r4[j];
                    float4 qv = q4[j];
                    a0 = fmaf(qv.x, mv.x, a0);
                    a1 = fmaf(qv.y, mv.y, a1);
                    a2 = fmaf(qv.z, mv.z, a2);
                    a3 = fmaf(qv.w, mv.w, a3);
                }
                snew = ((a0 + a1) + (a2 + a3)) * PSCALAR;
                mx = fmaxf(mx, snew);
            }
            if (i < FCAND) sCand[wid][i].y = __float_as_int(snew);
            else g_cand[cbase + i].y = __float_as_int(snew);
        }
        __syncwarp();
#pragma unroll
        for (int off = 16; off; off >>= 1)
            mx = fmaxf(mx, __shfl_xor_sync(0xFFFFFFFFu, mx, off));

        // pass B: deterministic fixed-point exp sum over exact-window terms
        float thE = mx - DELTAE;
        unsigned long long iacc = 0;
        for (int i = lane; i < c; i += 32) {
            float s = __int_as_float((i < FCAND) ? sCand[wid][i].y : g_cand[cbase + i].y);
            if (s > thE) {
                float w = expf(s - mx);
                iacc += (unsigned long long)((double)w * 4503599627370496.0);  // 2^52
            }
        }
#pragma unroll
        for (int off = 16; off; off >>= 1)
            iacc += __shfl_xor_sync(0xFFFFFFFFu, iacc, off);
        double dsum = (double)iacc * (1.0 / 4503599627370496.0);
        inv = (float)(1.0 / dsum);

        // pass C: ascending-m extraction + contiguous mvT row gather
        float ov[16];
#pragma unroll
        for (int j = 0; j < 16; j++) ov[j] = 0.f;

        const float* mvT = g_mvT + (size_t)b * NM * DV;
        int last = -1;
        while (true) {
            int mym = 0x7FFFFFFF; float myw = 0.f;
            for (int i = lane; i < c; i += 32) {
                int2 e = (i < FCAND) ? sCand[wid][i] : g_cand[cbase + i];
                float s = __int_as_float(e.y);
                if (s > thE && e.x > last && e.x < mym) {
                    mym = e.x;
                    myw = expf(s - mx);
                }
            }
#pragma unroll
            for (int off = 16; off; off >>= 1) {
                int om = __shfl_xor_sync(0xFFFFFFFFu, mym, off);
                float ow = __shfl_xor_sync(0xFFFFFFFFu, myw, off);
                if (om < mym) { mym = om; myw = ow; }
            }
            if (mym == 0x7FFFFFFF) break;
            const float* row = mvT + (size_t)mym * DV;
#pragma unroll
            for (int j = 0; j < 16; j++)
                ov[j] += myw * row[lane + 32 * j];
            last = mym;
        }

#pragma unroll
        for (int j = 0; j < 16; j++)
            sO[wid][lane + 32 * j] = ov[j] * inv;
    }
    __syncthreads();

    float* ob = out + (size_t)b * DV * NQ;
    for (int idx = tid; idx < 8 * DV; idx += NTHREADS) {
        int v = idx >> 3, k = idx & 7;
        int qgk = sQg[k];
        if (qgk >= 0) ob[(size_t)v * NQ + qgk] = sO[k][v];
    }
}

// -------- launch --------
extern "C" void kernel_launch(void* const* d_in, const int* in_sizes, int n_in,
                              void* d_out, int out_size) {
    const float*        qkey  = (const float*)d_in[0];
    // d_in[1] = qval (unused by the reference math)
    const unsigned int* qmask = (const unsigned int*)d_in[2];
    const float*        mkey  = (const float*)d_in[3];
    const float*        mval  = (const float*)d_in[4];
    const unsigned int* mmask = (const unsigned int*)d_in[5];
    float* out = (float*)d_out;

    compact_kernel<<<dim3(BATCH, 2), NTHREADS>>>(qmask, mmask);

    packtrans_kernel<<<PK_BLKS + TR_BLKS + ZO_BLKS, NTHREADS>>>(qkey, mkey, mval, (float4*)out);

    cudaFuncSetAttribute(qk_mma_kernel, cudaFuncAttributeMaxDynamicSharedMemorySize, SMQ_TOTAL);
    qk_mma_kernel<<<GRIDX, NTHREADS, SMQ_TOTAL>>>();

    // launch #4 — ncu capture slot: finalize
    finalize_kernel<<<dim3(NQ / 8, BATCH), NTHREADS>>>(qkey, out);
}

// round 17
// speedup vs baseline: 1.2073x; 1.0009x over previous
#include <cuda_runtime.h>
#include <cuda_bf16.h>
#include <cstdint>
#include <math.h>

// Problem shapes (fixed for this bench)
#define BATCH 2
#define DK 128
#define DV 512
#define NQ 4096         // H*W
#define NM 8192         // T*H*W
#define NTHREADS 256
#define PSCALAR 40.0f
// -ln(1e-12) + 8.0 slack for bf16 screening error (~11 sigma)
#define DELTAS 35.6310211159f
#define DELTAE 27.6310211159f   // exact window for final softmax terms

#define QTILE 128
#define MC 64
#define NSEG 12
#define GRIDX 384
#define CAP 1024
#define FCAND 64

// qk smem layout (bytes): A 128 rows x 256B + 2 B bufs of 64 rows x 256B
#define SMQ_A 512
#define SMQ_B (512 + 32768)
#define SMQ_TOTAL (SMQ_B + 2 * 16384)   // 66048 B -> 3 CTAs/SM

// packtrans role block counts
#define PK_BLKS  ((NQ + NM) / 32 * 2 * BATCH)              // 1536
#define TR_BLKS  ((NM / 32) * ((DK + DV) / 32) * BATCH)    // 10240
#define ZO_BLKS  ((BATCH * DV * NQ / 4) / NTHREADS)        // 4096

typedef unsigned long long ull;

// -------- device scratch (static: no allocations allowed) --------
__device__ uint32_t g_qkr[(size_t)BATCH * NQ * 64];   // packed bf16x2 rows [b][q][kp]
__device__ uint32_t g_mkr[(size_t)BATCH * NM * 64];   // packed bf16x2 rows [b][m][kp]
__device__ float    g_mkT[(size_t)BATCH * NM * DK];   // exact mkey rows [b][m][d]
__device__ float    g_mvT[(size_t)BATCH * NM * DV];   // exact mval rows [b][m][v]
__device__ int      g_qlist[BATCH * NQ];
__device__ int      g_mlist[BATCH * NM];
__device__ int      g_nq[BATCH];
__device__ int      g_nm[BATCH];
__device__ int2     g_cand[(size_t)BATCH * NQ * CAP];  // (m_compact, logit bits)
__device__ int      g_ccnt[BATCH * NQ];
__device__ unsigned g_qmax[BATCH * NQ];                // cross-segment running screened max

__device__ __forceinline__ unsigned fenc(float f) {
    unsigned u = __float_as_uint(f);
    return (u & 0x80000000u) ? ~u : (u | 0x80000000u);
}
__device__ __forceinline__ float fdec(unsigned e) {
    unsigned u = (e & 0x80000000u) ? (e & 0x7FFFFFFFu) : ~e;
    return __uint_as_float(u);
}
__device__ __forceinline__ uint32_t smem_u32(const void* p) {
    uint32_t a;
    asm("{ .reg .u64 t; cvta.to.shared.u64 t, %1; cvt.u32.u64 %0, t; }" : "=r"(a) : "l"(p));
    return a;
}

#define MMA_BF16(c0, c1, c2, c3, a0, a1, a2, a3, b0, b1) \
    asm volatile("mma.sync.aligned.m16n8k16.row.col.f32.bf16.bf16.f32 " \
        "{%0,%1,%2,%3}, {%4,%5,%6,%7}, {%8,%9}, {%0,%1,%2,%3};" \
        : "+f"(c0), "+f"(c1), "+f"(c2), "+f"(c3) \
        : "r"(a0), "r"(a1), "r"(a2), "r"(a3), "r"(b0), "r"(b1))

#define LDSM_X4(r0, r1, r2, r3, addr) \
    asm volatile("ldmatrix.sync.aligned.m8n8.x4.shared.b16 {%0,%1,%2,%3}, [%4];" \
        : "=r"(r0), "=r"(r1), "=r"(r2), "=r"(r3) : "r"(addr))

// -------- kernel 1: deterministic stream compaction + ccnt/qmax init --------
__global__ void compact_kernel(const unsigned int* qmask, const unsigned int* mmask) {
    int b = blockIdx.x;
    int which = blockIdx.y;    // 0 = q, 1 = m
    const unsigned int* mask = which ? (mmask + b * NM) : (qmask + b * NQ);
    int n = which ? NM : NQ;
    int* list = which ? (g_mlist + b * NM) : (g_qlist + b * NQ);

    {
        int blk = b * 2 + which;   // 0..3
        int per = BATCH * NQ / 4;
        unsigned neg = fenc(-3.0e38f);
        for (int i = threadIdx.x; i < per; i += NTHREADS) {
            g_ccnt[blk * per + i] = 0;
            g_qmax[blk * per + i] = neg;
        }
    }

    __shared__ int wcnt[NTHREADS / 32];
    __shared__ int sbase;
    int tid = threadIdx.x, lane = tid & 31, wid = tid >> 5;
    if (tid == 0) sbase = 0;
    __syncthreads();

    for (int start = 0; start < n; start += NTHREADS) {
        int idx = start + tid;
        int flag = (idx < n) && (mask[idx] != 0u);
        unsigned bal = __ballot_sync(0xFFFFFFFFu, flag);
        int pre = __popc(bal & ((1u << lane) - 1u));
        if (lane == 0) wcnt[wid] = __popc(bal);
        __syncthreads();
        int wbase = 0, tot = 0;
#pragma unroll
        for (int w = 0; w < NTHREADS / 32; w++) {
            if (w < wid) wbase += wcnt[w];
            tot += wcnt[w];
        }
        int base = sbase;
        if (flag) list[base + wbase + pre] = idx;
        __syncthreads();
        if (tid == 0) sbase = base + tot;
        __syncthreads();
    }
    if (tid == 0) {
        if (which) g_nm[b] = sbase; else g_nq[b] = sbase;
    }
}

// -------- kernel 2: fused pack (bf16 rows) + transpose (exact rows) + output zero --------
__global__ void packtrans_kernel(const float* __restrict__ qkey, const float* __restrict__ mkey,
                                 const float* __restrict__ mval, float4* __restrict__ out) {
    __shared__ float t[32][66];
    int bx = blockIdx.x;
    int tid = threadIdx.x;
    int tx = tid & 31, ty = tid >> 5;   // 32 x 8

    if (bx < PK_BLKS) {
        int rb = bx % ((NQ + NM) / 32);
        int half = (bx / ((NQ + NM) / 32)) & 1;
        int b = bx / ((NQ + NM) / 32 * 2);
        bool isq = rb < (NQ / 32);
        int base = isq ? rb * 32 : (rb - NQ / 32) * 32;
        int n = isq ? g_nq[b] : g_nm[b];
        int N = isq ? NQ : NM;
        const int* list = (isq ? g_qlist : g_mlist) + b * N;
        const float* src = (isq ? qkey : mkey) + (size_t)(b * DK + half * 64) * N;
        uint32_t* dst = (isq ? g_qkr : g_mkr) + ((size_t)b * N + base) * 64 + half * 32;

        int i = base + tx;
        int g = (i < n) ? list[i] : -1;
#pragma unroll
        for (int dd = ty; dd < 64; dd += 8)
            t[tx][dd] = (g >= 0) ? src[(size_t)dd * N + g] : 0.f;
        __syncthreads();
#pragma unroll
        for (int mi = ty; mi < 32; mi += 8) {
            float2 v = *(float2*)&t[mi][2 * tx];
            __nv_bfloat162 w = __floats2bfloat162_rn(v.x, v.y);
            dst[(size_t)mi * 64 + tx] = *(uint32_t*)&w;
        }
    } else if (bx < PK_BLKS + TR_BLKS) {
        int idx = bx - PK_BLKS;
        int m0 = (idx % (NM / 32)) * 32;
        int d0 = ((idx / (NM / 32)) % ((DK + DV) / 32)) * 32;
        int b = idx / ((NM / 32) * ((DK + DV) / 32));
        int nm = g_nm[b];
        if (m0 >= nm) return;
        bool ismk = d0 < DK;
        const float* src = ismk ? (mkey + (size_t)(b * DK + d0) * NM)
                                : (mval + (size_t)b * DV * NM + (size_t)(d0 - DK) * NM);
        int mg = (m0 + tx < nm) ? g_mlist[b * NM + m0 + tx] : 0;
#pragma unroll
        for (int i = ty; i < 32; i += 8)
            t[tx][i] = src[(size_t)i * NM + mg];
        __syncthreads();
#pragma unroll
        for (int i = ty; i < 32; i += 8) {
            int m = m0 + i;
            if (m < nm) {
                if (ismk) g_mkT[((size_t)b * NM + m) * DK + d0 + tx] = t[i][tx];
                else      g_mvT[((size_t)b * NM + m) * DV + (d0 - DK) + tx] = t[i][tx];
            }
        }
    } else {
        int idx = (bx - PK_BLKS - TR_BLKS) * NTHREADS + tid;
        out[idx] = make_float4(0.f, 0.f, 0.f, 0.f);
    }
}

// -------- kernel 3: bf16 mma.sync screening GEMM + cross-segment global suppression --------
__global__ __launch_bounds__(NTHREADS, 3)
void qk_mma_kernel() {
    extern __shared__ char smem[];
    uint32_t sbase = smem_u32(smem);
    unsigned* sGMax = (unsigned*)smem;
    uint32_t sAu = sbase + SMQ_A, sBu = sbase + SMQ_B;

    int tid = threadIdx.x, lane = tid & 31, wid = tid >> 5;
    int gr = lane >> 2, tig = lane & 3;
    int warp_q0 = (wid >> 2) * 64;
    int warp_m0 = (wid & 3) * 16;

    int nt0 = (g_nm[0] > 0) ? ((g_nq[0] + 127) >> 7) : 0;
    int nt1 = (g_nm[1] > 0) ? ((g_nq[1] + 127) >> 7) : 0;
    int total = (nt0 + nt1) * NSEG;

    int a_row_off = (lane & 15);
    int a_k16 = (lane >> 4) << 4;
    int b_row_off = (lane & 7) + ((lane & 16) >> 1);
    int b_k16 = (lane & 8) << 1;

    for (int item = blockIdx.x; item < total; item += gridDim.x) {
        int tq = item / NSEG, seg = item - tq * NSEG;
        int b = (tq < nt0) ? 0 : 1;
        int qt = (tq < nt0) ? tq : tq - nt0;
        int nq = g_nq[b], nm = g_nm[b];
        int qi0 = qt * QTILE;
        int segsz = ((((nm + NSEG - 1) / NSEG) + MC - 1) / MC) * MC;
        int ms = seg * segsz;
        if (ms >= nm) continue;
        int me = min(ms + segsz, nm);
        int nch = (me - ms + MC - 1) / MC;

        __syncthreads();
        if (tid < QTILE) {
            int q = qi0 + tid;
            sGMax[tid] = (q < nq) ? g_qmax[b * NQ + q] : fenc(-3.0e38f);
        }

        {
            const uint32_t* arows = g_qkr + ((size_t)b * NQ + qi0) * 64;
#pragma unroll
            for (int k2 = 0; k2 < 8; k2++) {
                int idx = tid + k2 * NTHREADS;
                int row = idx >> 4, ch = idx & 15;
                uint32_t doff = (uint32_t)((row << 8) + (ch << 4));
                doff ^= (uint32_t)((row & 7) << 4);
                const uint32_t* src = arows + row * 64 + ch * 4;
                asm volatile("cp.async.cg.shared.global [%0], [%1], 16;"
                             :: "r"(sAu + doff), "l"(src));
            }
            asm volatile("cp.async.commit_group;");
        }

        auto issueB = [&](int m0, int buf) {
            const uint32_t* brows = g_mkr + ((size_t)b * NM + m0) * 64;
            uint32_t bb = sBu + buf * 16384;
#pragma unroll
            for (int k2 = 0; k2 < 4; k2++) {
                int idx = tid + k2 * NTHREADS;
                int row = idx >> 4, ch = idx & 15;
                uint32_t doff = (uint32_t)((row << 8) + (ch << 4));
                doff ^= (uint32_t)((row & 7) << 4);
                const uint32_t* src = brows + row * 64 + ch * 4;
                asm volatile("cp.async.cg.shared.global [%0], [%1], 16;"
                             :: "r"(bb + doff), "l"(src));
            }
            asm volatile("cp.async.commit_group;");
        };

        issueB(ms, 0);

        for (int c = 0; c < nch; c++) {
            int mt0 = ms + c * MC;
            asm volatile("cp.async.wait_group 0;");
            __syncthreads();
            if (c + 1 < nch) issueB(ms + (c + 1) * MC, (c + 1) & 1);

            uint32_t sBc = sBu + (c & 1) * 16384;

            float acc[4][2][4];
#pragma unroll
            for (int qf = 0; qf < 4; qf++)
#pragma unroll
                for (int nf = 0; nf < 2; nf++)
#pragma unroll
                    for (int r = 0; r < 4; r++) acc[qf][nf][r] = 0.f;

#pragma unroll
            for (int s = 0; s < 8; s++) {
                uint32_t a[4][4], bf[4];
#pragma unroll
                for (int qf = 0; qf < 4; qf++) {
                    int row = warp_q0 + qf * 16 + a_row_off;
                    uint32_t off = (uint32_t)((row << 8) + (s << 5) + a_k16)
                                 ^ (uint32_t)((row & 7) << 4);
                    LDSM_X4(a[qf][0], a[qf][1], a[qf][2], a[qf][3], sAu + off);
                }
                {
                    int row = warp_m0 + b_row_off;
                    uint32_t off = (uint32_t)((row << 8) + (s << 5) + b_k16)
                                 ^ (uint32_t)((row & 7) << 4);
                    LDSM_X4(bf[0], bf[1], bf[2], bf[3], sBc + off);
                }
#pragma unroll
                for (int qf = 0; qf < 4; qf++)
#pragma unroll
                    for (int nf = 0; nf < 2; nf++)
                        MMA_BF16(acc[qf][nf][0], acc[qf][nf][1], acc[qf][nf][2], acc[qf][nf][3],
                                 a[qf][0], a[qf][1], a[qf][2], a[qf][3],
                                 bf[nf * 2], bf[nf * 2 + 1]);
            }

            int mbw = mt0 + warp_m0;
#pragma unroll
            for (int qf = 0; qf < 4; qf++) {
#pragma unroll
                for (int h = 0; h < 2; h++) {
                    int qrow = warp_q0 + qf * 16 + gr + h * 8;
                    int q = qi0 + qrow;
                    float sv[4];
                    float bm = -3.0e38f;
#pragma unroll
                    for (int nf = 0; nf < 2; nf++)
#pragma unroll
                        for (int col = 0; col < 2; col++) {
                            int ii = nf * 2 + col;
                            sv[ii] = acc[qf][nf][h * 2 + col] * PSCALAR;
                            int mg = mbw + nf * 8 + 2 * tig + col;
                            if (mg < me) bm = fmaxf(bm, sv[ii]);
                        }
                    if (q < nq && bm > fdec(sGMax[qrow]) - DELTAS) {
                        unsigned eb = fenc(bm);
                        unsigned olde = atomicMax(&sGMax[qrow], eb);
                        unsigned oldg = atomicMax(&g_qmax[b * NQ + q], eb);
                        float th = fmaxf(fmaxf(fdec(olde), fdec(oldg)), bm);
#pragma unroll
                        for (int nf = 0; nf < 2; nf++)
#pragma unroll
                            for (int col = 0; col < 2; col++) {
                                int ii = nf * 2 + col;
                                int mg = mbw + nf * 8 + 2 * tig + col;
                                if (mg < me && sv[ii] > th - DELTAS) {
                                    int pos = atomicAdd(&g_ccnt[b * NQ + q], 1);
                                    if (pos < CAP)
                                        g_cand[((size_t)b * NQ + q) * CAP + pos] =
                                            make_int2(mg, __float_as_int(sv[ii]));
                                }
                            }
                    }
                }
            }
        }
    }
}

// -------- kernel 4: finalize — lane-parallel exact logits + bitonic-sorted gather --------
__global__ __launch_bounds__(NTHREADS)
void finalize_kernel(const float* __restrict__ qkey, float* __restrict__ out) {
    __shared__ __align__(16) float sQc[8 * DK];   // 4 KB
    __shared__ int2  sCand[8][FCAND];             // 4 KB
    __shared__ float sO[8][DV + 4];               // 16.1 KB
    __shared__ int   sQg[8];
    int b = blockIdx.y;
    int nq = g_nq[b], nm = g_nm[b];
    if (nm == 0) return;
    int tid = threadIdx.x, wid = tid >> 5, lane = tid & 31;
    int q = blockIdx.x * 8 + wid;
    bool valid = (q < nq);

    int qg = 0, c = 0;
    size_t cbase = 0;
    if (valid) {
        qg = g_qlist[b * NQ + q];
        cbase = ((size_t)b * NQ + q) * CAP;
        c = min(g_ccnt[b * NQ + q], CAP);
    }
    if (lane == 0) sQg[wid] = valid ? qg : -1;

    if (valid) {
        for (int d = lane; d < DK; d += 32)
            sQc[wid * DK + d] = qkey[(size_t)(b * DK + d) * NQ + qg];
        for (int i = lane; i < c && i < FCAND; i += 32)
            sCand[wid][i] = g_cand[cbase + i];
    }
    __syncwarp();

    float inv = 0.f, mx = -3.0e38f;
    if (valid) {
        float mxs = -3.0e38f;
        for (int i = lane; i < c; i += 32) {
            int2 e = (i < FCAND) ? sCand[wid][i] : g_cand[cbase + i];
            mxs = fmaxf(mxs, __int_as_float(e.y));
        }
#pragma unroll
        for (int off = 16; off; off >>= 1)
            mxs = fmaxf(mxs, __shfl_xor_sync(0xFFFFFFFFu, mxs, off));

        // pass A: lane-parallel exact fp32 logits
        const float* mkT = g_mkT + (size_t)b * NM * DK;
        const float4* q4 = (const float4*)&sQc[wid * DK];
        for (int i = lane; i < c; i += 32) {
            int2 e = (i < FCAND) ? sCand[wid][i] : g_cand[cbase + i];
            float snew = -3.0e38f;
            if (__int_as_float(e.y) > mxs - DELTAS) {
                const float4* r4 = (const float4*)(mkT + (size_t)e.x * DK);
                float a0 = 0.f, a1 = 0.f, a2 = 0.f, a3 = 0.f;
#pragma unroll 8
                for (int j = 0; j < DK / 4; j++) {
                    float4 mv = r4[j];
                    float4 qv = q4[j];
                    a0 = fmaf(qv.x, mv.x, a0);
                    a1 = fmaf(qv.y, mv.y, a1);
                    a2 = fmaf(qv.z, mv.z, a2);
                    a3 = fmaf(qv.w, mv.w, a3);
                }
                snew = ((a0 + a1) + (a2 + a3)) * PSCALAR;
                mx = fmaxf(mx, snew);
            }
            if (i < FCAND) sCand[wid][i].y = __float_as_int(snew);
            else g_cand[cbase + i].y = __float_as_int(snew);
        }
        __syncwarp();
#pragma unroll
        for (int off = 16; off; off >>= 1)
            mx = fmaxf(mx, __shfl_xor_sync(0xFFFFFFFFu, mx, off));

        // pass B: deterministic fixed-point exp sum over exact-window terms
        float thE = mx - DELTAE;
        unsigned long long iacc = 0;
        for (int i = lane; i < c; i += 32) {
            float s = __int_as_float((i < FCAND) ? sCand[wid][i].y : g_cand[cbase + i].y);
            if (s > thE) {
                float w = expf(s - mx);
                iacc += (unsigned long long)((double)w * 4503599627370496.0);  // 2^52
            }
        }
#pragma unroll
        for (int off = 16; off; off >>= 1)
            iacc += __shfl_xor_sync(0xFFFFFFFFu, iacc, off);
        double dsum = (double)iacc * (1.0 / 4503599627370496.0);
        inv = (float)(1.0 / dsum);

        // pass C: ordered gather of kept events
        float ov[16];
#pragma unroll
        for (int j = 0; j < 16; j++) ov[j] = 0.f;

        const float* mvT = g_mvT + (size_t)b * NM * DV;

        if (c <= 32) {
            // fast path: one candidate per lane, bitonic sort by m ascending
            int myM = 0x7FFFFFFF; float myW = 0.f;
            if (lane < c) {
                int2 e = sCand[wid][lane];
                float s = __int_as_float(e.y);
                if (s > thE) { myM = e.x; myW = expf(s - mx); }
            }
#pragma unroll
            for (int k = 2; k <= 32; k <<= 1) {
#pragma unroll
                for (int j = k >> 1; j > 0; j >>= 1) {
                    int om = __shfl_xor_sync(0xFFFFFFFFu, myM, j);
                    float ow = __shfl_xor_sync(0xFFFFFFFFu, myW, j);
                    bool ascend = ((lane & k) == 0);
                    bool isLower = ((lane & j) == 0);
                    bool keepMin = (ascend == isLower);
                    bool take = keepMin ? (om < myM) : (om > myM);
                    if (take) { myM = om; myW = ow; }
                }
            }
            int cnt = __popc(__ballot_sync(0xFFFFFFFFu, myM != 0x7FFFFFFF));
            int e = 0;
            for (; e + 1 < cnt; e += 2) {
                int m0 = __shfl_sync(0xFFFFFFFFu, myM, e);
                float w0 = __shfl_sync(0xFFFFFFFFu, myW, e);
                int m1 = __shfl_sync(0xFFFFFFFFu, myM, e + 1);
                float w1 = __shfl_sync(0xFFFFFFFFu, myW, e + 1);
                const float* r0 = mvT + (size_t)m0 * DV;
                const float* r1 = mvT + (size_t)m1 * DV;
#pragma unroll
                for (int j = 0; j < 16; j++) {
                    float v0 = r0[lane + 32 * j];
                    float v1 = r1[lane + 32 * j];
                    ov[j] += w0 * v0;
                    ov[j] += w1 * v1;
                }
            }
            if (e < cnt) {
                int m0 = __shfl_sync(0xFFFFFFFFu, myM, e);
                float w0 = __shfl_sync(0xFFFFFFFFu, myW, e);
                const float* r0 = mvT + (size_t)m0 * DV;
#pragma unroll
                for (int j = 0; j < 16; j++)
                    ov[j] += w0 * r0[lane + 32 * j];
            }
        } else {
            // slow path: serial ascending-m extraction
            int last = -1;
            while (true) {
                int mym = 0x7FFFFFFF; float myw = 0.f;
                for (int i = lane; i < c; i += 32) {
                    int2 e = (i < FCAND) ? sCand[wid][i] : g_cand[cbase + i];
                    float s = __int_as_float(e.y);
                    if (s > thE && e.x > last && e.x < mym) {
                        mym = e.x;
                        myw = expf(s - mx);
                    }
                }
#pragma unroll
                for (int off = 16; off; off >>= 1) {
                    int om = __shfl_xor_sync(0xFFFFFFFFu, mym, off);
                    float ow = __shfl_xor_sync(0xFFFFFFFFu, myw, off);
                    if (om < mym) { mym = om; myw = ow; }
                }
                if (mym == 0x7FFFFFFF) break;
                const float* row = mvT + (size_t)mym * DV;
#pragma unroll
                for (int j = 0; j < 16; j++)
                    ov[j] += myw * row[lane + 32 * j];
                last = mym;
            }
        }

#pragma unroll
        for (int j = 0; j < 16; j++)
            sO[wid][lane + 32 * j] = ov[j] * inv;
    }
    __syncthreads();

    float* ob = out + (size_t)b * DV * NQ;
    for (int idx = tid; idx < 8 * DV; idx += NTHREADS) {
        int v = idx >> 3, k = idx & 7;
        int qgk = sQg[k];
        if (qgk >= 0) ob[(size_t)v * NQ + qgk] = sO[k][v];
    }
}

// -------- launch --------
extern "C" void kernel_launch(void* const* d_in, const int* in_sizes, int n_in,
                              void* d_out, int out_size) {
    const float*        qkey  = (const float*)d_in[0];
    // d_in[1] = qval (unused by the reference math)
    const unsigned int* qmask = (const unsigned int*)d_in[2];
    const float*        mkey  = (const float*)d_in[3];
    const float*        mval  = (const float*)d_in[4];
    const unsigned int* mmask = (const unsigned int*)d_in[5];
    float* out = (float*)d_out;

    compact_kernel<<<dim3(BATCH, 2), NTHREADS>>>(qmask, mmask);

    packtrans_kernel<<<PK_BLKS + TR_BLKS + ZO_BLKS, NTHREADS>>>(qkey, mkey, mval, (float4*)out);

    cudaFuncSetAttribute(qk_mma_kernel, cudaFuncAttributeMaxDynamicSharedMemorySize, SMQ_TOTAL);
    qk_mma_kernel<<<GRIDX, NTHREADS, SMQ_TOTAL>>>();

    // launch #4 — ncu capture slot: finalize
    finalize_kernel<<<dim3(NQ / 8, BATCH), NTHREADS>>>(qkey, out);
}